// round 4
// baseline (speedup 1.0000x reference)
#include <cuda_runtime.h>
#include <cstdint>

// Output layout (float32):
//   [0, 16384)                 : out_bounds [2,32,16,16]
//   [16384, 16384+8192*8192)   : W_mat [8192, 8192]
//   then [+8192)               : bias_backsub [8192]
#define OUT_FEAT 8192
#define IN_FEAT  8192
#define BOUNDS_BLOCKS 1024   // 8 warps/block, one warp per output element
#define WMAT_BLOCKS   65536  // flat: one float4 per thread (R1 geometry, 6.2 TB/s)

__global__ void __launch_bounds__(256) fused_kernel(
        const float* __restrict__ bounds,
        const float* __restrict__ weight,
        const float* __restrict__ bias,
        float* __restrict__ out_bounds,
        float4* __restrict__ wmat,
        float* __restrict__ bias_backsub) {
    if (blockIdx.x >= BOUNDS_BLOCKS) {
        // ------------------------------------------------------------------
        // W_mat fill: flat one-shot threads, 1 x STG.128 each (R1 geometry).
        // W_mat[(co,ho,wo),(ci,h,w)] = weight[co,ci,h-(2ho-1),w-(2wo-1)]
        // when both kernel offsets land in [0,4), else 0.
        // ------------------------------------------------------------------
        unsigned t = (blockIdx.x - BOUNDS_BLOCKS) * 256u + threadIdx.x; // 0..16777215
        unsigned o = t >> 11;           // row (2048 float4 per row)
        unsigned i = (t & 2047u) << 2;  // starting column element

        int co = o >> 8;
        int ho = (o >> 4) & 15;
        int wo = o & 15;
        int ci = i >> 10;
        int h  = (i >> 5) & 31;
        int w  = i & 31;

        int kh  = h - (ho * 2 - 1);
        int kw0 = w - (wo * 2 - 1);

        float4 v = make_float4(0.f, 0.f, 0.f, 0.f);
        if ((unsigned)kh < 4u) {
            const float* wp = weight + ((co * 8 + ci) * 4 + kh) * 4;
            if ((unsigned)(kw0    ) < 4u) v.x = __ldg(wp + kw0);
            if ((unsigned)(kw0 + 1) < 4u) v.y = __ldg(wp + kw0 + 1);
            if ((unsigned)(kw0 + 2) < 4u) v.z = __ldg(wp + kw0 + 2);
            if ((unsigned)(kw0 + 3) < 4u) v.w = __ldg(wp + kw0 + 3);
        }
        wmat[t] = v;
    } else {
        // ------------------------------------------------------------------
        // Bounds + bias_backsub: one warp per output element. The reference's
        // back-substituted bound equals the forward interval bound (same
        // linear map scattered into W_mat), so the where()-tighten collapses.
        // Scheduled in the FIRST wave so it hides under the wmat stream.
        // ------------------------------------------------------------------
        int warp = (int)blockIdx.x * 8 + (threadIdx.x >> 5);   // 0..8191
        int lane = threadIdx.x & 31;

        int co = warp >> 8;
        int ho = (warp >> 4) & 15;
        int wo = warp & 15;

        const float* l = bounds;           // [8,32,32]
        const float* u = bounds + 8192;

        float lo = 0.f, up = 0.f;
#pragma unroll
        for (int j = 0; j < 4; ++j) {
            int idx = lane * 4 + j;        // ci*16 + kh*4 + kw  (128 terms)
            int ci = idx >> 4;
            int kh = (idx >> 2) & 3;
            int kw = idx & 3;
            int h = ho * 2 - 1 + kh;       // stride 2, pad 1
            int w = wo * 2 - 1 + kw;
            if ((unsigned)h < 32u && (unsigned)w < 32u) {
                float wt = __ldg(&weight[((co * 8 + ci) * 4 + kh) * 4 + kw]);
                float wp = fmaxf(wt, 0.f);
                float wm = fminf(wt, 0.f);
                int ii = ci * 1024 + h * 32 + w;
                float lv = __ldg(&l[ii]);
                float uv = __ldg(&u[ii]);
                lo = fmaf(wp, lv, fmaf(wm, uv, lo));
                up = fmaf(wp, uv, fmaf(wm, lv, up));
            }
        }
#pragma unroll
        for (int off = 16; off; off >>= 1) {
            lo += __shfl_down_sync(0xffffffffu, lo, off);
            up += __shfl_down_sync(0xffffffffu, up, off);
        }
        if (lane == 0) {
            float b = __ldg(&bias[co]);
            out_bounds[warp]            = lo + b;   // lower
            out_bounds[OUT_FEAT + warp] = up + b;   // upper
            bias_backsub[warp]          = b;        // repeat_interleave(bias,256)
        }
    }
}

extern "C" void kernel_launch(void* const* d_in, const int* in_sizes, int n_in,
                              void* d_out, int out_size) {
    const float* bounds = (const float*)d_in[0];  // [2,8,32,32]
    const float* weight = (const float*)d_in[1];  // [32,8,4,4]
    const float* bias   = (const float*)d_in[2];  // [32]
    // d_in[3] = assignment (unused by forward)

    float* out          = (float*)d_out;
    float* out_bounds   = out;
    float* wmat         = out + 16384;
    float* bias_backsub = out + 16384 + (size_t)OUT_FEAT * IN_FEAT;

    fused_kernel<<<BOUNDS_BLOCKS + WMAT_BLOCKS, 256>>>(
        bounds, weight, bias, out_bounds, (float4*)wmat, bias_backsub);
}

// round 6
// speedup vs baseline: 1.2109x; 1.2109x over previous
#include <cuda_runtime.h>
#include <cstdint>

// Output layout (float32):
//   [0, 16384)                 : out_bounds [2,32,16,16]
//   [16384, 16384+8192*8192)   : W_mat [8192, 8192]
//   then [+8192)               : bias_backsub [8192]
#define OUT_FEAT 8192
#define IN_FEAT  8192
// grid = 66560 blocks of 256 threads.
// blockIdx % 65 == 64  -> bounds block   (1024 blocks, spread through grid)
// otherwise            -> wmat block     (65536 blocks, flat R1 geometry)

__global__ void __launch_bounds__(256) fused_kernel(
        const float* __restrict__ bounds,
        const float* __restrict__ weight,
        const float* __restrict__ bias,
        float* __restrict__ out_bounds,
        float4* __restrict__ wmat,
        float* __restrict__ bias_backsub) {
    unsigned b = blockIdx.x;
    unsigned m = b % 65u;
    if (m != 64u) {
        // ------------------------------------------------------------------
        // W_mat fill: flat, one float4 (STG.128, evict-first) per thread.
        // W_mat[(co,ho,wo),(ci,h,w)] = weight[co,ci,h-(2ho-1),w-(2wo-1)]
        // when both kernel offsets land in [0,4), else 0.
        // ------------------------------------------------------------------
        unsigned wb = b - b / 65u;                    // wmat block ordinal 0..65535
        unsigned t  = wb * 256u + threadIdx.x;        // 0..16777215
        unsigned o  = t >> 11;                        // row (2048 float4/row)
        unsigned i  = (t & 2047u) << 2;               // starting column element

        int co = o >> 8;
        int ho = (o >> 4) & 15;
        int wo = o & 15;
        int ci = i >> 10;
        int h  = (i >> 5) & 31;
        int w  = i & 31;

        int kh  = h - (ho * 2 - 1);
        int kw0 = w - (wo * 2 - 1);

        float4 v = make_float4(0.f, 0.f, 0.f, 0.f);
        if ((unsigned)kh < 4u) {
            const float* wp = weight + ((co * 8 + ci) * 4 + kh) * 4;
            if ((unsigned)(kw0    ) < 4u) v.x = __ldg(wp + kw0);
            if ((unsigned)(kw0 + 1) < 4u) v.y = __ldg(wp + kw0 + 1);
            if ((unsigned)(kw0 + 2) < 4u) v.z = __ldg(wp + kw0 + 2);
            if ((unsigned)(kw0 + 3) < 4u) v.w = __ldg(wp + kw0 + 3);
        }
        __stcs(wmat + t, v);
    } else {
        // ------------------------------------------------------------------
        // Bounds + bias_backsub: one warp per output element, spread through
        // the grid so the latency-bound loads hide under the store stream.
        // Back-substituted bound == forward interval bound (same linear map),
        // so the reference's where()-tighten collapses to this value.
        // ------------------------------------------------------------------
        int warp = (int)(b / 65u) * 8 + (threadIdx.x >> 5);   // 0..8191
        int lane = threadIdx.x & 31;

        int co = warp >> 8;
        int ho = (warp >> 4) & 15;
        int wo = warp & 15;

        const float* l = bounds;           // [8,32,32]
        const float* u = bounds + 8192;

        float lo = 0.f, up = 0.f;
#pragma unroll
        for (int j = 0; j < 4; ++j) {
            int idx = lane * 4 + j;        // ci*16 + kh*4 + kw  (128 terms)
            int ci = idx >> 4;
            int kh = (idx >> 2) & 3;
            int kw = idx & 3;
            int h = ho * 2 - 1 + kh;       // stride 2, pad 1
            int w = wo * 2 - 1 + kw;
            if ((unsigned)h < 32u && (unsigned)w < 32u) {
                float wt = __ldg(&weight[((co * 8 + ci) * 4 + kh) * 4 + kw]);
                float wp = fmaxf(wt, 0.f);
                float wm = fminf(wt, 0.f);
                int ii = ci * 1024 + h * 32 + w;
                float lv = __ldg(&l[ii]);
                float uv = __ldg(&u[ii]);
                lo = fmaf(wp, lv, fmaf(wm, uv, lo));
                up = fmaf(wp, uv, fmaf(wm, lv, up));
            }
        }
#pragma unroll
        for (int off = 16; off; off >>= 1) {
            lo += __shfl_down_sync(0xffffffffu, lo, off);
            up += __shfl_down_sync(0xffffffffu, up, off);
        }
        if (lane == 0) {
            float bb = __ldg(&bias[co]);
            out_bounds[warp]            = lo + bb;   // lower
            out_bounds[OUT_FEAT + warp] = up + bb;   // upper
            bias_backsub[warp]          = bb;        // repeat_interleave(bias,256)
        }
    }
}

extern "C" void kernel_launch(void* const* d_in, const int* in_sizes, int n_in,
                              void* d_out, int out_size) {
    const float* bounds = (const float*)d_in[0];  // [2,8,32,32]
    const float* weight = (const float*)d_in[1];  // [32,8,4,4]
    const float* bias   = (const float*)d_in[2];  // [32]
    // d_in[3] = assignment (unused by forward)

    float* out          = (float*)d_out;
    float* out_bounds   = out;
    float* wmat         = out + 16384;
    float* bias_backsub = out + 16384 + (size_t)OUT_FEAT * IN_FEAT;

    fused_kernel<<<66560, 256>>>(
        bounds, weight, bias, out_bounds, (float4*)wmat, bias_backsub);
}

// round 7
// speedup vs baseline: 1.2361x; 1.0208x over previous
#include <cuda_runtime.h>
#include <cstdint>

// Output layout (float32):
//   [0, 16384)                 : out_bounds [2,32,16,16]
//   [16384, 16384+8192*8192)   : W_mat [8192, 8192]
//   then [+8192)               : bias_backsub [8192]
#define OUT_FEAT 8192
#define IN_FEAT  8192
// grid = 33792 blocks of 256 threads.
//   blockIdx % 33 == 32 -> bounds block (1024, spread through the grid)
//   otherwise           -> wmat block   (32768; each thread stores quads
//                          t and t+8388608, which share all index decode
//                          since they differ only by co -> co+16)
#define HALF_QUADS 8388608u   // 4096 rows * 2048 quads

__global__ void __launch_bounds__(256) fused_kernel(
        const float* __restrict__ bounds,
        const float* __restrict__ weight,
        const float* __restrict__ bias,
        float* __restrict__ out_bounds,
        float4* __restrict__ wmat,
        float* __restrict__ bias_backsub) {
    unsigned b = blockIdx.x;
    unsigned m = b % 33u;
    if (m != 32u) {
        // ------------------------------------------------------------------
        // W_mat fill. W_mat[(co,ho,wo),(ci,h,w)] = weight[co,ci,h-hb,w-wb]
        // when offsets land in [0,4), else 0; hb=2ho-1, wb=2wo-1.
        // Quad t and quad t+HALF_QUADS share (ho,wo,ci,h,w): decode once.
        // ------------------------------------------------------------------
        unsigned wb_ = b - b / 33u;                   // wmat block ordinal 0..32767
        unsigned t   = wb_ * 256u + threadIdx.x;      // 0..8388607
        unsigned o   = t >> 11;                       // row 0..4095 (co 0..15)
        unsigned i   = (t & 2047u) << 2;              // starting column element

        int co = o >> 8;                              // 0..15
        int ho = (o >> 4) & 15;
        int wo = o & 15;
        int ci = i >> 10;
        int h  = (i >> 5) & 31;
        int w  = i & 31;

        int kh  = h - (ho * 2 - 1);
        int kw0 = w - (wo * 2 - 1);

        float4 v0 = make_float4(0.f, 0.f, 0.f, 0.f);
        float4 v1 = v0;
        if ((unsigned)kh < 4u) {
            const float* wp0 = weight + ((co * 8 + ci) * 4 + kh) * 4;
            const float* wp1 = wp0 + 16 * 128;        // co + 16 slab
            if ((unsigned)(kw0    ) < 4u) { v0.x = __ldg(wp0 + kw0);     v1.x = __ldg(wp1 + kw0);     }
            if ((unsigned)(kw0 + 1) < 4u) { v0.y = __ldg(wp0 + kw0 + 1); v1.y = __ldg(wp1 + kw0 + 1); }
            if ((unsigned)(kw0 + 2) < 4u) { v0.z = __ldg(wp0 + kw0 + 2); v1.z = __ldg(wp1 + kw0 + 2); }
            if ((unsigned)(kw0 + 3) < 4u) { v0.w = __ldg(wp0 + kw0 + 3); v1.w = __ldg(wp1 + kw0 + 3); }
        }
        __stcs(wmat + t, v0);
        __stcs(wmat + t + HALF_QUADS, v1);
    } else {
        // ------------------------------------------------------------------
        // Bounds + bias_backsub: one warp per output element, interleaved
        // through the grid so its latency hides under the store stream.
        // Back-substituted bound == forward interval bound (same linear map),
        // so the reference's where()-tighten collapses to this value.
        // ------------------------------------------------------------------
        int warp = (int)(b / 33u) * 8 + (threadIdx.x >> 5);   // 0..8191
        int lane = threadIdx.x & 31;

        int co = warp >> 8;
        int ho = (warp >> 4) & 15;
        int wo = warp & 15;

        const float* l = bounds;           // [8,32,32]
        const float* u = bounds + 8192;

        float lo = 0.f, up = 0.f;
#pragma unroll
        for (int j = 0; j < 4; ++j) {
            int idx = lane * 4 + j;        // ci*16 + kh*4 + kw  (128 terms)
            int ci = idx >> 4;
            int kh = (idx >> 2) & 3;
            int kw = idx & 3;
            int h = ho * 2 - 1 + kh;       // stride 2, pad 1
            int w = wo * 2 - 1 + kw;
            if ((unsigned)h < 32u && (unsigned)w < 32u) {
                float wt = __ldg(&weight[((co * 8 + ci) * 4 + kh) * 4 + kw]);
                float wp = fmaxf(wt, 0.f);
                float wm = fminf(wt, 0.f);
                int ii = ci * 1024 + h * 32 + w;
                float lv = __ldg(&l[ii]);
                float uv = __ldg(&u[ii]);
                lo = fmaf(wp, lv, fmaf(wm, uv, lo));
                up = fmaf(wp, uv, fmaf(wm, lv, up));
            }
        }
#pragma unroll
        for (int off = 16; off; off >>= 1) {
            lo += __shfl_down_sync(0xffffffffu, lo, off);
            up += __shfl_down_sync(0xffffffffu, up, off);
        }
        if (lane == 0) {
            float bb = __ldg(&bias[co]);
            out_bounds[warp]            = lo + bb;   // lower
            out_bounds[OUT_FEAT + warp] = up + bb;   // upper
            bias_backsub[warp]          = bb;        // repeat_interleave(bias,256)
        }
    }
}

extern "C" void kernel_launch(void* const* d_in, const int* in_sizes, int n_in,
                              void* d_out, int out_size) {
    const float* bounds = (const float*)d_in[0];  // [2,8,32,32]
    const float* weight = (const float*)d_in[1];  // [32,8,4,4]
    const float* bias   = (const float*)d_in[2];  // [32]
    // d_in[3] = assignment (unused by forward)

    float* out          = (float*)d_out;
    float* out_bounds   = out;
    float* wmat         = out + 16384;
    float* bias_backsub = out + 16384 + (size_t)OUT_FEAT * IN_FEAT;

    fused_kernel<<<33792, 256>>>(
        bounds, weight, bias, out_bounds, (float4*)wmat, bias_backsub);
}